// round 8
// baseline (speedup 1.0000x reference)
#include <cuda_runtime.h>

#define NPTS 4096
#define NW 128            // max bitset words (4096/32)
#define NPROB 4           // (b, class) pairs
#define ACAP 1536         // shared alive-list capacity (M <= ~1400 expected)
#define SEC  4096         // shared edge capacity
#define EMAX (1 << 20)    // global edge capacity per problem (expected ~2K)

static __device__ float4             g_pt[NPROB][NPTS];   // compacted valid pts (z,y,x,aa)
static __device__ unsigned long long g_key[NPROB][NPTS];  // order key (asc = higher priority)
static __device__ unsigned           g_edges[NPROB][EMAX];// (succ<<12)|pred
static __device__ int                g_ecnt[NPROB];
static __device__ int                g_M[NPROB];
static __device__ float4             g_aovf[NPROB][NPTS]; // alive-list overflow (unlikely)

// XLA logistic(x) = 0.5 + 0.5*tanh(0.5x), Eigen rational tanh
__device__ __forceinline__ float xla_logistic(float x) {
    float t  = 0.5f * x;
    float ax = fabsf(t);
    float xc = fminf(fmaxf(t, -7.90531110763549805f), 7.90531110763549805f);
    float x2 = xc * xc;
    float p = fmaf(x2, -2.76076847742355e-16f, 2.00018790482477e-13f);
    p = fmaf(x2, p, -8.60467152213735e-11f);
    p = fmaf(x2, p,  5.12229709037114e-08f);
    p = fmaf(x2, p,  1.48572235717979e-05f);
    p = fmaf(x2, p,  6.37261928875436e-04f);
    p = fmaf(x2, p,  4.89352455891786e-03f);
    p = xc * p;
    float q = fmaf(x2, 1.19825839466702e-06f, 1.18534705686654e-04f);
    q = fmaf(x2, q, 2.26843463243900e-03f);
    q = fmaf(x2, q, 4.89352518554385e-03f);
    float y = p / q;
    if (ax < 0.0004f) y = t;
    return __fadd_rn(__fmul_rn(0.5f, y), 0.5f);
}

__device__ __forceinline__ bool conflict_test(float4 pi, float4 pj, float c2) {
    float dot = __fadd_rn(__fadd_rn(__fmul_rn(pi.x, pj.x),
                                    __fmul_rn(pi.y, pj.y)),
                          __fmul_rn(pi.z, pj.z));
    float dist = __fsub_rn(__fadd_rn(pi.w, pj.w), __fmul_rn(2.0f, dot));
    return dist < c2;
}

// ---------------------------------------------------------------------------
// Kernel 1: conf/argmax; compact valid points with positions + priority keys.
// ---------------------------------------------------------------------------
__global__ __launch_bounds__(1024, 1) void k_prep(
    const float* __restrict__ pred_clses,
    const float* __restrict__ pred_boxes)
{
    __shared__ int sM;
    int prob = blockIdx.x;
    int b    = prob >> 1;
    int cls  = (prob & 1) + 1;
    int tid  = threadIdx.x;

    if (tid == 0) { sM = 0; g_ecnt[prob] = 0; }
    __syncthreads();

    for (int n = tid; n < NPTS; n += 1024) {
        float cv0 = pred_clses[(b * 3 + 0) * NPTS + n];
        float cv1 = pred_clses[(b * 3 + 1) * NPTS + n];
        float cv2 = pred_clses[(b * 3 + 2) * NPTS + n];
        float conf = cv0; int arg = 0;
        if (cv1 > conf) { conf = cv1; arg = 1; }
        if (cv2 > conf) { conf = cv2; arg = 2; }
        if (arg != cls) continue;

        int d = n >> 10, h = (n >> 5) & 31, w = n & 31;
        float sz = xla_logistic(pred_boxes[(b * 3 + 0) * NPTS + n]);
        float sy = xla_logistic(pred_boxes[(b * 3 + 1) * NPTS + n]);
        float sx = xla_logistic(pred_boxes[(b * 3 + 2) * NPTS + n]);
        float pz = __fmul_rn(__fdiv_rn(__fadd_rn((float)d, sz),  4.0f),  3.0f);
        float py = __fmul_rn(__fdiv_rn(__fadd_rn((float)h, sy), 32.0f), 25.0f);
        float px = __fmul_rn(__fdiv_rn(__fadd_rn((float)w, sx), 32.0f), 25.0f);
        float aa = __fadd_rn(__fadd_rn(__fmul_rn(pz, pz), __fmul_rn(py, py)),
                             __fmul_rn(px, px));

        unsigned cb  = __float_as_uint(conf);
        unsigned ord = cb ^ ((cb & 0x80000000u) ? 0xFFFFFFFFu : 0x80000000u);
        unsigned long long key = (((unsigned long long)(~ord)) << 32) | (unsigned)n;

        int slot = atomicAdd(&sM, 1);
        g_pt[prob][slot]  = make_float4(pz, py, px, aa);
        g_key[prob][slot] = key;
    }
    __syncthreads();
    if (tid == 0) g_M[prob] = sM;
}

// ---------------------------------------------------------------------------
// Kernel 2: sparse conflict edges — thread per j, plain unrolled scan of i<j.
// Hits are rare (~1/thread): direct global atomic emit, no ballots.
// ---------------------------------------------------------------------------
__device__ __forceinline__ void emit_edge(int prob, int i, int j,
                                          const unsigned long long* key,
                                          unsigned long long kj)
{
    int e = atomicAdd(&g_ecnt[prob], 1);
    if (e < EMAX) {
        unsigned pred, succ;
        if (key[i] < kj) { pred = (unsigned)i; succ = (unsigned)j; }
        else             { pred = (unsigned)j; succ = (unsigned)i; }
        g_edges[prob][e] = (succ << 12) | pred;
    }
}

__global__ __launch_bounds__(256) void k_edges()
{
    int prob = blockIdx.y;
    int M    = g_M[prob];
    float c2 = (prob & 1) ? 0.5625f : 1.0f;
    int nthr = gridDim.x * blockDim.x;
    int gt   = blockIdx.x * blockDim.x + threadIdx.x;
    const float4* __restrict__ pt = g_pt[prob];
    const unsigned long long* __restrict__ key = g_key[prob];

    for (int j = gt; j < M; j += nthr) {
        float4 pj = pt[j];
        unsigned long long kj = key[j];
        int i = 0;
        for (; i + 4 <= j; i += 4) {
            float4 p0 = pt[i], p1 = pt[i+1], p2 = pt[i+2], p3 = pt[i+3];
            bool h0 = conflict_test(p0, pj, c2);
            bool h1 = conflict_test(p1, pj, c2);
            bool h2 = conflict_test(p2, pj, c2);
            bool h3 = conflict_test(p3, pj, c2);
            if (h0) emit_edge(prob, i,     j, key, kj);
            if (h1) emit_edge(prob, i + 1, j, key, kj);
            if (h2) emit_edge(prob, i + 2, j, key, kj);
            if (h3) emit_edge(prob, i + 3, j, key, kj);
        }
        for (; i < j; i++) {
            if (conflict_test(pt[i], pj, c2)) emit_edge(prob, i, j, key, kj);
        }
    }
}

// ---------------------------------------------------------------------------
// Kernel 3: NMS on sparse edges (edges staged in SHARED) + survivor
// compaction to shared + target matching + output. One block per problem.
// ---------------------------------------------------------------------------
__global__ __launch_bounds__(1024, 1) void k_nms_match(
    const int*   __restrict__ targ_clses,
    const float* __restrict__ targ_boxes,
    float*       __restrict__ out)
{
    __shared__ unsigned alive[NW], Fb[NW], bF[NW], bA[NW];
    __shared__ int sChanged, sCount, sLP, sLT, sTP;
    __shared__ float4 s_al[ACAP];     // 24 KB
    __shared__ unsigned s_ed[SEC];    // 16 KB

    int prob = blockIdx.x;
    int b    = prob >> 1;
    int cls  = (prob & 1) + 1;
    float c2 = (prob & 1) ? 0.5625f : 1.0f;
    const float HI = (float)(3.0 + 1e-05);
    int tid  = threadIdx.x;
    int lane = tid & 31;
    int M    = g_M[prob];
    int E    = g_ecnt[prob]; if (E > EMAX) E = EMAX;

    // stage edges into shared (generic-pointer fallback if E > SEC, ~never)
    const unsigned* __restrict__ ep;
    if (E <= SEC) {
        for (int e = tid; e < E; e += 1024) s_ed[e] = g_edges[prob][e];
        ep = s_ed;
    } else {
        ep = g_edges[prob];
    }

    if (tid < NW) {
        int fullw = M >> 5, rem = M & 31;
        unsigned v = 0;
        if (tid < fullw) v = 0xFFFFFFFFu;
        else if (tid == fullw && rem) v = (1u << rem) - 1u;
        alive[tid] = v;
    }
    if (tid == 0) { sCount = 0; sLP = 0; sLT = 0; sTP = 0; }
    __syncthreads();

    for (int it = 0; it < 32; it++) {
        if (tid < NW) bF[tid] = 0;
        if (tid == 0) sChanged = 0;
        __syncthreads();
        // pass 1: bF[s] |= alive[p]   ->  F = alive & ~bF
        for (int e = tid; e < E; e += 1024) {
            unsigned w = ep[e];
            int p = w & 0xFFF, s = w >> 12;
            if ((alive[p >> 5] >> (p & 31)) & 1)
                atomicOr(&bF[s >> 5], 1u << (s & 31));
        }
        __syncthreads();
        if (tid < NW) { Fb[tid] = alive[tid] & ~bF[tid]; bA[tid] = 0; }
        __syncthreads();
        // pass 2: bA[s] |= F[p]  ->  alive &= ~bA
        for (int e = tid; e < E; e += 1024) {
            unsigned w = ep[e];
            int p = w & 0xFFF, s = w >> 12;
            if ((Fb[p >> 5] >> (p & 31)) & 1)
                atomicOr(&bA[s >> 5], 1u << (s & 31));
        }
        __syncthreads();
        if (tid < NW) {
            unsigned na = alive[tid] & ~bA[tid];
            if (na != alive[tid]) sChanged = 1;
            alive[tid] = na;
        }
        __syncthreads();
        int stop = (sChanged == 0);   // fixed point => later iters identical
        __syncthreads();
        if (stop) break;
    }

    // compact survivors into shared; count lp (z in [0, HI))
    for (int s = tid; s < M; s += 1024) {
        if ((alive[s >> 5] >> (s & 31)) & 1) {
            float4 p = g_pt[prob][s];
            int id = atomicAdd(&sCount, 1);
            if (id < ACAP) s_al[id] = p;
            else           g_aovf[prob][id] = p;
            if (p.x >= 0.0f && p.x < HI) atomicAdd(&sLP, 1);
        }
    }
    __syncthreads();

    int A  = sCount;
    int Ak = A < ACAP ? A : ACAP;

    // match targets against shared alive list (8-way unrolled)
    int ltc = 0, tpc = 0;
    for (int n = tid; n < NPTS; n += 1024) {
        if (targ_clses[b * NPTS + n] != cls) continue;
        int d = n >> 10, h = (n >> 5) & 31, w = n & 31;
        float t0 = targ_boxes[(b * NPTS + n) * 3 + 0];
        float t1 = targ_boxes[(b * NPTS + n) * 3 + 1];
        float t2 = targ_boxes[(b * NPTS + n) * 3 + 2];
        float tz = __fmul_rn(__fdiv_rn(__fadd_rn((float)d, t0),  4.0f),  3.0f);
        float ty = __fmul_rn(__fdiv_rn(__fadd_rn((float)h, t1), 32.0f), 25.0f);
        float tx = __fmul_rn(__fdiv_rn(__fadd_rn((float)w, t2), 32.0f), 25.0f);
        if (!(tz >= 0.0f && tz < HI)) continue;
        ltc++;
        float bb = __fadd_rn(__fadd_rn(__fmul_rn(tz, tz), __fmul_rn(ty, ty)),
                             __fmul_rn(tx, tx));
        float4 tq = make_float4(tz, ty, tx, bb);
        bool found = false;
        for (int a0 = 0; a0 < Ak && !found; a0 += 8) {
            bool hit = false;
            #pragma unroll
            for (int k = 0; k < 8; k++) {
                int a = a0 + k;
                if (a < Ak) hit |= conflict_test(s_al[a], tq, c2);
            }
            found = hit;
        }
        for (int a = ACAP; a < A && !found; a++)      // overflow fallback
            found = conflict_test(g_aovf[prob][a], tq, c2);
        if (found) tpc++;
    }
    ltc = __reduce_add_sync(0xFFFFFFFFu, ltc);
    tpc = __reduce_add_sync(0xFFFFFFFFu, tpc);
    if (lane == 0) {
        if (ltc) atomicAdd(&sLT, ltc);
        if (tpc) atomicAdd(&sTP, tpc);
    }
    __syncthreads();

    if (tid == 0) {
        int tp = sTP, lp = sLP, lt = sLT;
        out[prob * 3 + 0] = (float)tp;
        out[prob * 3 + 1] = (float)(lp - tp);
        out[prob * 3 + 2] = (float)(lt - tp);
    }
}

extern "C" void kernel_launch(void* const* d_in, const int* in_sizes, int n_in,
                              void* d_out, int out_size)
{
    const float* pred_clses = (const float*)d_in[0];
    const float* pred_boxes = (const float*)d_in[1];
    const int*   targ_clses = (const int*)d_in[2];
    const float* targ_boxes = (const float*)d_in[3];
    float* out = (float*)d_out;

    k_prep<<<NPROB, 1024>>>(pred_clses, pred_boxes);
    k_edges<<<dim3(16, NPROB), 256>>>();
    k_nms_match<<<NPROB, 1024>>>(targ_clses, targ_boxes, out);
}

// round 9
// speedup vs baseline: 3.4686x; 3.4686x over previous
#include <cuda_runtime.h>

#define NPTS   4096
#define NPROB  4
#define PCAP   2048            // max valid points per problem (M ~ 1365)
#define NWORD  (PCAP / 32)     // 64 bitset words
#define SEC    6144            // shared edge capacity (E ~ 2-3K)
#define GEC    65536           // global overflow edge capacity (safety)

static __device__ unsigned g_eovf[NPROB][GEC];   // edge overflow (normally unused)

// XLA logistic(x) = 0.5 + 0.5*tanh(0.5x), Eigen rational tanh (bit-matched)
__device__ __forceinline__ float xla_logistic(float x) {
    float t  = 0.5f * x;
    float ax = fabsf(t);
    float xc = fminf(fmaxf(t, -7.90531110763549805f), 7.90531110763549805f);
    float x2 = xc * xc;
    float p = fmaf(x2, -2.76076847742355e-16f, 2.00018790482477e-13f);
    p = fmaf(x2, p, -8.60467152213735e-11f);
    p = fmaf(x2, p,  5.12229709037114e-08f);
    p = fmaf(x2, p,  1.48572235717979e-05f);
    p = fmaf(x2, p,  6.37261928875436e-04f);
    p = fmaf(x2, p,  4.89352455891786e-03f);
    p = xc * p;
    float q = fmaf(x2, 1.19825839466702e-06f, 1.18534705686654e-04f);
    q = fmaf(x2, q, 2.26843463243900e-03f);
    q = fmaf(x2, q, 4.89352518554385e-03f);
    float y = p / q;
    if (ax < 0.0004f) y = t;
    return __fadd_rn(__fmul_rn(0.5f, y), 0.5f);
}

// Shared layout (dynamic):
//   s_pt   float4[PCAP]   32768 B   (.x=z .y=y .z=x .w=priority bits)
//   s_ed   uint  [SEC]    24576 B   (succ<<12 | pred)
//   s_slot short [NPTS]    8192 B   (cell -> slot, -1 invalid)
//   s_bits uint  [4*NWORD] 1024 B   (alive, F, bF, bA)
//   s_cnt  int   [8]         32 B
#define OFF_PT    0
#define OFF_ED    32768
#define OFF_SLOT  (32768 + 24576)
#define OFF_BITS  (OFF_SLOT + 8192)
#define OFF_CNT   (OFF_BITS + 1024)
#define SMEM_TOTAL (OFF_CNT + 32)

__global__ __launch_bounds__(1024, 1) void k_fused(
    const float* __restrict__ pred_clses,
    const float* __restrict__ pred_boxes,
    const int*   __restrict__ targ_clses,
    const float* __restrict__ targ_boxes,
    float*       __restrict__ out)
{
    extern __shared__ __align__(16) unsigned char smem[];
    float4*   s_pt   = (float4*)(smem + OFF_PT);
    unsigned* s_ed   = (unsigned*)(smem + OFF_ED);
    short*    s_slot = (short*)(smem + OFF_SLOT);
    unsigned* alive  = (unsigned*)(smem + OFF_BITS);
    unsigned* Fb     = alive + NWORD;
    unsigned* bF     = alive + 2 * NWORD;
    unsigned* bA     = alive + 3 * NWORD;
    int*      s_cnt  = (int*)(smem + OFF_CNT);
    // s_cnt: 0=M, 1=E, 2=changed, 3=lp, 4=lt, 5=tp

    int prob = blockIdx.x;
    int b    = prob >> 1;
    int cls  = (prob & 1) + 1;
    float c2 = (prob & 1) ? 0.5625f : 1.0f;
    const float HI = (float)(3.0 + 1e-05);
    int tid  = threadIdx.x;
    int lane = tid & 31;

    // ---- phase 0: init ----
    if (tid < 8) s_cnt[tid] = 0;
    for (int n = tid; n < NPTS; n += 1024) s_slot[n] = -1;
    __syncthreads();

    // ---- phase 1: conf/argmax, positions, slot map ----
    for (int n = tid; n < NPTS; n += 1024) {
        float cv0 = pred_clses[(b * 3 + 0) * NPTS + n];
        float cv1 = pred_clses[(b * 3 + 1) * NPTS + n];
        float cv2 = pred_clses[(b * 3 + 2) * NPTS + n];
        float conf = cv0; int arg = 0;
        if (cv1 > conf) { conf = cv1; arg = 1; }
        if (cv2 > conf) { conf = cv2; arg = 2; }
        if (arg != cls) continue;

        int d = n >> 10, h = (n >> 5) & 31, w = n & 31;
        float sz = xla_logistic(pred_boxes[(b * 3 + 0) * NPTS + n]);
        float sy = xla_logistic(pred_boxes[(b * 3 + 1) * NPTS + n]);
        float sx = xla_logistic(pred_boxes[(b * 3 + 2) * NPTS + n]);
        float pz = __fmul_rn(__fdiv_rn(__fadd_rn((float)d, sz),  4.0f),  3.0f);
        float py = __fmul_rn(__fdiv_rn(__fadd_rn((float)h, sy), 32.0f), 25.0f);
        float px = __fmul_rn(__fdiv_rn(__fadd_rn((float)w, sx), 32.0f), 25.0f);

        // priority bits: ascending == (conf desc); cell-index breaks ties
        unsigned cb  = __float_as_uint(conf);
        unsigned ord = cb ^ ((cb & 0x80000000u) ? 0xFFFFFFFFu : 0x80000000u);
        unsigned po  = ~ord;

        int slot = atomicAdd(&s_cnt[0], 1);
        if (slot < PCAP) {
            s_pt[slot] = make_float4(pz, py, px, __uint_as_float(po));
            s_slot[n]  = (short)slot;
        }
    }
    __syncthreads();
    int M = s_cnt[0]; if (M > PCAP) M = PCAP;

    // alive init
    if (tid < NWORD) {
        int fw = M >> 5, rem = M & 31;
        unsigned v = 0;
        if (tid < fw) v = 0xFFFFFFFFu;
        else if (tid == fw && rem) v = (1u << rem) - 1u;
        alive[tid] = v;
    }

    // ---- phase 2: conflict edges via 5x5x5 half-stencil ----
    // Any pair at offsets with >= two coords of |2| has min dist^2 > 1.17 > c2.
    for (int n = tid; n < NPTS; n += 1024) {
        int j = s_slot[n]; if (j < 0) continue;
        float4 pj = s_pt[j];
        float aaj = __fadd_rn(__fadd_rn(__fmul_rn(pj.x, pj.x), __fmul_rn(pj.y, pj.y)),
                              __fmul_rn(pj.z, pj.z));
        unsigned poj = __float_as_uint(pj.w);
        int d = n >> 10, h = (n >> 5) & 31, w = n & 31;

        for (int dz = -2; dz <= 2; dz++) {
            int d2 = d + dz; if (d2 < 0 || d2 > 3) continue;
            int t_z = (dz == 2 || dz == -2);
            for (int dy = -2; dy <= 2; dy++) {
                int h2 = h + dy; if (h2 < 0 || h2 > 31) continue;
                int t_zy = t_z + (dy == 2 || dy == -2);
                if (t_zy >= 2) continue;
                for (int dx = -2; dx <= 2; dx++) {
                    int w2 = w + dx; if (w2 < 0 || w2 > 31) continue;
                    if (t_zy + (dx == 2 || dx == -2) >= 2) continue;
                    // half-stencil: lexicographically positive offsets only
                    if (!(dz > 0 || (dz == 0 && (dy > 0 || (dy == 0 && dx > 0))))) continue;
                    int n2 = (d2 << 10) | (h2 << 5) | w2;
                    int i = s_slot[n2]; if (i < 0) continue;
                    float4 pi = s_pt[i];
                    float aai = __fadd_rn(__fadd_rn(__fmul_rn(pi.x, pi.x),
                                                    __fmul_rn(pi.y, pi.y)),
                                          __fmul_rn(pi.z, pi.z));
                    float dot = __fadd_rn(__fadd_rn(__fmul_rn(pi.x, pj.x),
                                                    __fmul_rn(pi.y, pj.y)),
                                          __fmul_rn(pi.z, pj.z));
                    float dist = __fsub_rn(__fadd_rn(aai, aaj), __fmul_rn(2.0f, dot));
                    if (dist < c2) {
                        unsigned poi = __float_as_uint(pi.w);
                        unsigned pred, succ;
                        if (poi < poj || (poi == poj && n2 < n)) { pred = (unsigned)i; succ = (unsigned)j; }
                        else                                     { pred = (unsigned)j; succ = (unsigned)i; }
                        int e = atomicAdd(&s_cnt[1], 1);
                        unsigned pk = (succ << 12) | pred;
                        if (e < SEC)            s_ed[e] = pk;
                        else if (e < SEC + GEC) g_eovf[prob][e - SEC] = pk;
                    }
                }
            }
        }
    }
    __syncthreads();
    int E  = s_cnt[1];
    int Es = E < SEC ? E : SEC;
    int Eg = E - SEC; if (Eg < 0) Eg = 0; if (Eg > GEC) Eg = GEC;

    // ---- phase 3: NMS iterations (exact fixed-point early exit) ----
    for (int it = 0; it < 32; it++) {
        if (tid < NWORD) bF[tid] = 0;
        if (tid == 0) s_cnt[2] = 0;
        __syncthreads();
        // bF[s] |= alive[p]  ->  F = alive & ~bF
        for (int e = tid; e < Es; e += 1024) {
            unsigned pk = s_ed[e];
            int p = pk & 0xFFF, s = pk >> 12;
            if ((alive[p >> 5] >> (p & 31)) & 1)
                atomicOr(&bF[s >> 5], 1u << (s & 31));
        }
        for (int e = tid; e < Eg; e += 1024) {
            unsigned pk = g_eovf[prob][e];
            int p = pk & 0xFFF, s = pk >> 12;
            if ((alive[p >> 5] >> (p & 31)) & 1)
                atomicOr(&bF[s >> 5], 1u << (s & 31));
        }
        __syncthreads();
        if (tid < NWORD) { Fb[tid] = alive[tid] & ~bF[tid]; bA[tid] = 0; }
        __syncthreads();
        // bA[s] |= F[p]  ->  alive &= ~bA
        for (int e = tid; e < Es; e += 1024) {
            unsigned pk = s_ed[e];
            int p = pk & 0xFFF, s = pk >> 12;
            if ((Fb[p >> 5] >> (p & 31)) & 1)
                atomicOr(&bA[s >> 5], 1u << (s & 31));
        }
        for (int e = tid; e < Eg; e += 1024) {
            unsigned pk = g_eovf[prob][e];
            int p = pk & 0xFFF, s = pk >> 12;
            if ((Fb[p >> 5] >> (p & 31)) & 1)
                atomicOr(&bA[s >> 5], 1u << (s & 31));
        }
        __syncthreads();
        if (tid < NWORD) {
            unsigned na = alive[tid] & ~bA[tid];
            if (na != alive[tid]) s_cnt[2] = 1;
            alive[tid] = na;
        }
        __syncthreads();
        int stop = (s_cnt[2] == 0);
        __syncthreads();
        if (stop) break;
    }

    // ---- phase 4: lp (alive preds, z-range; pz always in [0,3) but keep) ----
    {
        int lpc = 0;
        for (int s = tid; s < M; s += 1024) {
            if ((alive[s >> 5] >> (s & 31)) & 1) {
                float zc = s_pt[s].x;
                if (zc >= 0.0f && zc < HI) lpc++;
            }
        }
        lpc = __reduce_add_sync(0xFFFFFFFFu, lpc);
        if (lane == 0 && lpc) atomicAdd(&s_cnt[3], lpc);
    }

    // ---- phase 5: target matching via full stencil (81 offsets) ----
    int ltc = 0, tpc = 0;
    for (int n = tid; n < NPTS; n += 1024) {
        if (targ_clses[b * NPTS + n] != cls) continue;
        int d = n >> 10, h = (n >> 5) & 31, w = n & 31;
        float t0 = targ_boxes[(b * NPTS + n) * 3 + 0];
        float t1 = targ_boxes[(b * NPTS + n) * 3 + 1];
        float t2 = targ_boxes[(b * NPTS + n) * 3 + 2];
        float tz = __fmul_rn(__fdiv_rn(__fadd_rn((float)d, t0),  4.0f),  3.0f);
        float ty = __fmul_rn(__fdiv_rn(__fadd_rn((float)h, t1), 32.0f), 25.0f);
        float tx = __fmul_rn(__fdiv_rn(__fadd_rn((float)w, t2), 32.0f), 25.0f);
        if (!(tz >= 0.0f && tz < HI)) continue;
        ltc++;
        float bbt = __fadd_rn(__fadd_rn(__fmul_rn(tz, tz), __fmul_rn(ty, ty)),
                              __fmul_rn(tx, tx));
        bool found = false;
        for (int dz = -2; dz <= 2 && !found; dz++) {
            int d2 = d + dz; if (d2 < 0 || d2 > 3) continue;
            int t_z = (dz == 2 || dz == -2);
            for (int dy = -2; dy <= 2 && !found; dy++) {
                int h2 = h + dy; if (h2 < 0 || h2 > 31) continue;
                int t_zy = t_z + (dy == 2 || dy == -2);
                if (t_zy >= 2) continue;
                for (int dx = -2; dx <= 2 && !found; dx++) {
                    int w2 = w + dx; if (w2 < 0 || w2 > 31) continue;
                    if (t_zy + (dx == 2 || dx == -2) >= 2) continue;
                    int n2 = (d2 << 10) | (h2 << 5) | w2;
                    int i = s_slot[n2]; if (i < 0) continue;
                    if (!((alive[i >> 5] >> (i & 31)) & 1)) continue;
                    float4 p = s_pt[i];
                    float aai = __fadd_rn(__fadd_rn(__fmul_rn(p.x, p.x),
                                                    __fmul_rn(p.y, p.y)),
                                          __fmul_rn(p.z, p.z));
                    float dot = __fadd_rn(__fadd_rn(__fmul_rn(p.x, tz),
                                                    __fmul_rn(p.y, ty)),
                                          __fmul_rn(p.z, tx));
                    float dist = __fsub_rn(__fadd_rn(aai, bbt), __fmul_rn(2.0f, dot));
                    if (dist < c2) found = true;
                }
            }
        }
        if (found) tpc++;
    }
    ltc = __reduce_add_sync(0xFFFFFFFFu, ltc);
    tpc = __reduce_add_sync(0xFFFFFFFFu, tpc);
    if (lane == 0) {
        if (ltc) atomicAdd(&s_cnt[4], ltc);
        if (tpc) atomicAdd(&s_cnt[5], tpc);
    }
    __syncthreads();

    // ---- phase 6: write counts as float32 ----
    if (tid == 0) {
        int tp = s_cnt[5], lp = s_cnt[3], lt = s_cnt[4];
        out[prob * 3 + 0] = (float)tp;
        out[prob * 3 + 1] = (float)(lp - tp);
        out[prob * 3 + 2] = (float)(lt - tp);
    }
}

extern "C" void kernel_launch(void* const* d_in, const int* in_sizes, int n_in,
                              void* d_out, int out_size)
{
    const float* pred_clses = (const float*)d_in[0];
    const float* pred_boxes = (const float*)d_in[1];
    const int*   targ_clses = (const int*)d_in[2];
    const float* targ_boxes = (const float*)d_in[3];
    float* out = (float*)d_out;

    cudaFuncSetAttribute(k_fused, cudaFuncAttributeMaxDynamicSharedMemorySize,
                         SMEM_TOTAL);
    k_fused<<<NPROB, 1024, SMEM_TOTAL>>>(pred_clses, pred_boxes,
                                         targ_clses, targ_boxes, out);
}

// round 13
// speedup vs baseline: 9.8815x; 2.8488x over previous
#include <cuda_runtime.h>

#define NPTS   4096
#define NPROB  4
#define NW     128             // 4096 cells / 32
#define EMAXG  (1 << 17)       // global edge capacity per problem
#define SEC    16384           // K3 shared edge stage capacity
#define BEC    2048            // K2 per-block shared edge buffer

static __device__ float4   g_pos[NPROB][NPTS];    // .x=z .y=y .z=x .w=priority bits
static __device__ unsigned g_vmask[NPROB][NW];    // valid-cell bitset
static __device__ unsigned g_alive[NPROB][NW];    // post-NMS alive bitset
static __device__ unsigned g_edges[NPROB][EMAXG]; // (succ<<12)|pred (cell ids)
static __device__ int      g_ecnt[NPROB];
static __device__ int      g_cnt[NPROB][3];       // tp, lp, lt

// XLA logistic(x) = 0.5 + 0.5*tanh(0.5x), Eigen rational tanh (bit-matched)
__device__ __forceinline__ float xla_logistic(float x) {
    float t  = 0.5f * x;
    float ax = fabsf(t);
    float xc = fminf(fmaxf(t, -7.90531110763549805f), 7.90531110763549805f);
    float x2 = xc * xc;
    float p = fmaf(x2, -2.76076847742355e-16f, 2.00018790482477e-13f);
    p = fmaf(x2, p, -8.60467152213735e-11f);
    p = fmaf(x2, p,  5.12229709037114e-08f);
    p = fmaf(x2, p,  1.48572235717979e-05f);
    p = fmaf(x2, p,  6.37261928875436e-04f);
    p = fmaf(x2, p,  4.89352455891786e-03f);
    p = xc * p;
    float q = fmaf(x2, 1.19825839466702e-06f, 1.18534705686654e-04f);
    q = fmaf(x2, q, 2.26843463243900e-03f);
    q = fmaf(x2, q, 4.89352518554385e-03f);
    float y = p / q;
    if (ax < 0.0004f) y = t;
    return __fadd_rn(__fmul_rn(0.5f, y), 0.5f);
}

// 5x5x5 stencil minus offsets with >=2 coords of |2| (min dist^2 there
// > 1.125 > cutoff^2).  half=1: lexicographically-positive offsets only
// (center drops out automatically).  half=0: FULL stencil INCLUDING the
// center cell — same-cell target/pred matches are the common case.
__device__ __forceinline__ void build_stencil(int tid, int half,
                                              int* tab, int* cnt)
{
    if (tid < 125) {
        int dz = tid / 25 - 2;
        int r  = tid % 25;
        int dy = r / 5 - 2;
        int dx = r % 5 - 2;
        int n2c = (dz == 2 || dz == -2) + (dy == 2 || dy == -2) +
                  (dx == 2 || dx == -2);
        bool keep = (n2c < 2);
        if (half)
            keep = keep && ((dz > 0) || (dz == 0 && (dy > 0 || (dy == 0 && dx > 0))));
        if (keep) {
            int s = atomicAdd(cnt, 1);
            tab[s] = (dz + 2) | ((dy + 2) << 3) | ((dx + 2) << 6);
        }
    }
}

// ---------------------------------------------------------------------------
// K1: per-cell conf/argmax, positions, validity bitset (warp ballot).
// grid (16, NPROB) x 256 — exactly one thread per cell.
// ---------------------------------------------------------------------------
__global__ __launch_bounds__(256) void k_prep(
    const float* __restrict__ pred_clses,
    const float* __restrict__ pred_boxes)
{
    int prob = blockIdx.y;
    int b    = prob >> 1;
    int cls  = (prob & 1) + 1;
    int tid  = threadIdx.x;
    int n    = blockIdx.x * 256 + tid;

    if (blockIdx.x == 0) {
        if (tid == 0) g_ecnt[prob] = 0;
        if (tid < 3)  g_cnt[prob][tid] = 0;
    }

    float cv0 = pred_clses[(b * 3 + 0) * NPTS + n];
    float cv1 = pred_clses[(b * 3 + 1) * NPTS + n];
    float cv2 = pred_clses[(b * 3 + 2) * NPTS + n];
    float conf = cv0; int arg = 0;
    if (cv1 > conf) { conf = cv1; arg = 1; }
    if (cv2 > conf) { conf = cv2; arg = 2; }
    bool valid = (arg == cls);

    unsigned bal = __ballot_sync(0xFFFFFFFFu, valid);
    if ((tid & 31) == 0) g_vmask[prob][n >> 5] = bal;

    if (valid) {
        int d = n >> 10, h = (n >> 5) & 31, w = n & 31;
        float sz = xla_logistic(pred_boxes[(b * 3 + 0) * NPTS + n]);
        float sy = xla_logistic(pred_boxes[(b * 3 + 1) * NPTS + n]);
        float sx = xla_logistic(pred_boxes[(b * 3 + 2) * NPTS + n]);
        float pz = __fmul_rn(__fdiv_rn(__fadd_rn((float)d, sz),  4.0f),  3.0f);
        float py = __fmul_rn(__fdiv_rn(__fadd_rn((float)h, sy), 32.0f), 25.0f);
        float px = __fmul_rn(__fdiv_rn(__fadd_rn((float)w, sx), 32.0f), 25.0f);
        // ascending priority == (conf desc); cell index breaks ties
        unsigned cb  = __float_as_uint(conf);
        unsigned ord = cb ^ ((cb & 0x80000000u) ? 0xFFFFFFFFu : 0x80000000u);
        g_pos[prob][n] = make_float4(pz, py, px, __uint_as_float(~ord));
    }
}

// ---------------------------------------------------------------------------
// K2: conflict edges via 40-offset half stencil.  grid (16, NPROB) x 256.
// ---------------------------------------------------------------------------
__global__ __launch_bounds__(256) void k_edges()
{
    __shared__ unsigned s_vm[NW];
    __shared__ unsigned s_eb[BEC];
    __shared__ int s_ne, s_nt, s_base, s_tab[40];

    int prob = blockIdx.y;
    float c2 = (prob & 1) ? 0.5625f : 1.0f;
    int tid  = threadIdx.x;

    if (tid == 0) { s_ne = 0; s_nt = 0; }
    for (int w = tid; w < NW; w += 256) s_vm[w] = g_vmask[prob][w];
    __syncthreads();
    build_stencil(tid, 1, s_tab, &s_nt);
    __syncthreads();

    int n = blockIdx.x * 256 + tid;
    if ((s_vm[n >> 5] >> (n & 31)) & 1) {
        float4 pj = g_pos[prob][n];
        float aaj = __fadd_rn(__fadd_rn(__fmul_rn(pj.x, pj.x),
                                        __fmul_rn(pj.y, pj.y)),
                              __fmul_rn(pj.z, pj.z));
        unsigned poj = __float_as_uint(pj.w);
        int d = n >> 10, h = (n >> 5) & 31, w0 = n & 31;

        #pragma unroll 4
        for (int k = 0; k < 40; k++) {
            int v  = s_tab[k];
            int d2 = d  + (v & 7) - 2;
            int h2 = h  + ((v >> 3) & 7) - 2;
            int w2 = w0 + ((v >> 6) & 7) - 2;
            if ((unsigned)d2 > 3u || (unsigned)h2 > 31u || (unsigned)w2 > 31u)
                continue;
            int n2 = (d2 << 10) | (h2 << 5) | w2;
            if (!((s_vm[n2 >> 5] >> (n2 & 31)) & 1)) continue;
            float4 pi = g_pos[prob][n2];
            float aai = __fadd_rn(__fadd_rn(__fmul_rn(pi.x, pi.x),
                                            __fmul_rn(pi.y, pi.y)),
                                  __fmul_rn(pi.z, pi.z));
            float dot = __fadd_rn(__fadd_rn(__fmul_rn(pi.x, pj.x),
                                            __fmul_rn(pi.y, pj.y)),
                                  __fmul_rn(pi.z, pj.z));
            float dist = __fsub_rn(__fadd_rn(aai, aaj), __fmul_rn(2.0f, dot));
            if (dist < c2) {
                unsigned poi = __float_as_uint(pi.w);
                unsigned pred, succ;
                if (poi < poj || (poi == poj && n2 < n)) { pred = (unsigned)n2; succ = (unsigned)n; }
                else                                     { pred = (unsigned)n;  succ = (unsigned)n2; }
                unsigned pk = (succ << 12) | pred;
                int e = atomicAdd(&s_ne, 1);
                if (e < BEC) s_eb[e] = pk;
                else {
                    int ge = atomicAdd(&g_ecnt[prob], 1);
                    if (ge < EMAXG) g_edges[prob][ge] = pk;
                }
            }
        }
    }
    __syncthreads();
    int ne = s_ne < BEC ? s_ne : BEC;
    if (tid == 0) s_base = atomicAdd(&g_ecnt[prob], ne);
    __syncthreads();
    for (int e = tid; e < ne; e += 256) {
        int ge = s_base + e;
        if (ge < EMAXG) g_edges[prob][ge] = s_eb[e];
    }
}

// ---------------------------------------------------------------------------
// K3: NMS fixed-point iterations on sparse edges (staged in shared).
// grid NPROB x 1024.  Writes alive bitset + lp.
// ---------------------------------------------------------------------------
__global__ __launch_bounds__(1024, 1) void k_nms()
{
    extern __shared__ unsigned dsm[];
    unsigned* alive = dsm;
    unsigned* Fb    = dsm + NW;
    unsigned* bF    = dsm + 2 * NW;
    unsigned* bA    = dsm + 3 * NW;
    unsigned* s_ed  = dsm + 4 * NW;
    __shared__ int s_ch, s_lp;

    int prob = blockIdx.x;
    int tid  = threadIdx.x;
    int E    = g_ecnt[prob]; if (E > EMAXG) E = EMAXG;
    int Es   = E < SEC ? E : SEC;

    for (int e = tid; e < Es; e += 1024) s_ed[e] = g_edges[prob][e];
    if (tid < NW) alive[tid] = g_vmask[prob][tid];
    if (tid == 0) s_lp = 0;
    __syncthreads();

    for (int it = 0; it < 32; it++) {
        if (tid < NW) bF[tid] = 0;
        if (tid == 0) s_ch = 0;
        __syncthreads();
        // pass 1: bF[s] |= alive[p]  ->  F = alive & ~bF
        for (int e = tid; e < Es; e += 1024) {
            unsigned pk = s_ed[e];
            int p = pk & 0xFFF, s = pk >> 12;
            if ((alive[p >> 5] >> (p & 31)) & 1)
                atomicOr(&bF[s >> 5], 1u << (s & 31));
        }
        for (int e = Es + tid; e < E; e += 1024) {
            unsigned pk = g_edges[prob][e];
            int p = pk & 0xFFF, s = pk >> 12;
            if ((alive[p >> 5] >> (p & 31)) & 1)
                atomicOr(&bF[s >> 5], 1u << (s & 31));
        }
        __syncthreads();
        if (tid < NW) { Fb[tid] = alive[tid] & ~bF[tid]; bA[tid] = 0; }
        __syncthreads();
        // pass 2: bA[s] |= F[p]  ->  alive &= ~bA
        for (int e = tid; e < Es; e += 1024) {
            unsigned pk = s_ed[e];
            int p = pk & 0xFFF, s = pk >> 12;
            if ((Fb[p >> 5] >> (p & 31)) & 1)
                atomicOr(&bA[s >> 5], 1u << (s & 31));
        }
        for (int e = Es + tid; e < E; e += 1024) {
            unsigned pk = g_edges[prob][e];
            int p = pk & 0xFFF, s = pk >> 12;
            if ((Fb[p >> 5] >> (p & 31)) & 1)
                atomicOr(&bA[s >> 5], 1u << (s & 31));
        }
        __syncthreads();
        if (tid < NW) {
            unsigned na = alive[tid] & ~bA[tid];
            if (na != alive[tid]) s_ch = 1;
            alive[tid] = na;
        }
        __syncthreads();
        int stop = (s_ch == 0);   // fixed point => all later iters identical
        __syncthreads();
        if (stop) break;
    }

    // lp = popcount(alive): pz in [0, 3.0] always (incl. logistic rounding
    // to 1.0), and 3.0 < 3+1e-5, so the z-range filter is vacuous.
    if (tid < NW) {
        int c = __popc(alive[tid]);
        c = __reduce_add_sync(0xFFFFFFFFu, c);
        if ((tid & 31) == 0 && c) atomicAdd(&s_lp, c);
        g_alive[prob][tid] = alive[tid];
    }
    __syncthreads();
    if (tid == 0) g_cnt[prob][1] = s_lp;
}

// ---------------------------------------------------------------------------
// K4: target matching via 81-offset full stencil (INCLUDING center) vs
// alive bitset.  grid (16, NPROB) x 256 — one thread per cell.
// ---------------------------------------------------------------------------
__global__ __launch_bounds__(256) void k_match(
    const int*   __restrict__ targ_clses,
    const float* __restrict__ targ_boxes)
{
    __shared__ unsigned s_al[NW];
    __shared__ int s_nt, s_tab[81], sLT, sTP;

    int prob = blockIdx.y;
    int b    = prob >> 1;
    int cls  = (prob & 1) + 1;
    float c2 = (prob & 1) ? 0.5625f : 1.0f;
    const float HI = (float)(3.0 + 1e-05);
    int tid  = threadIdx.x;

    if (tid == 0) { s_nt = 0; sLT = 0; sTP = 0; }
    for (int w = tid; w < NW; w += 256) s_al[w] = g_alive[prob][w];
    __syncthreads();
    build_stencil(tid, 0, s_tab, &s_nt);
    __syncthreads();
    int nt = s_nt;   // 81

    int n = blockIdx.x * 256 + tid;
    int lt = 0, tp = 0;
    if (targ_clses[b * NPTS + n] == cls) {
        int d = n >> 10, h = (n >> 5) & 31, w0 = n & 31;
        float t0 = targ_boxes[(b * NPTS + n) * 3 + 0];
        float t1 = targ_boxes[(b * NPTS + n) * 3 + 1];
        float t2 = targ_boxes[(b * NPTS + n) * 3 + 2];
        float tz = __fmul_rn(__fdiv_rn(__fadd_rn((float)d, t0),  4.0f),  3.0f);
        float ty = __fmul_rn(__fdiv_rn(__fadd_rn((float)h, t1), 32.0f), 25.0f);
        float tx = __fmul_rn(__fdiv_rn(__fadd_rn((float)w0, t2), 32.0f), 25.0f);
        if (tz >= 0.0f && tz < HI) {
            lt = 1;
            float bbt = __fadd_rn(__fadd_rn(__fmul_rn(tz, tz), __fmul_rn(ty, ty)),
                                  __fmul_rn(tx, tx));
            bool found = false;
            for (int k = 0; k < nt && !found; k++) {
                int v  = s_tab[k];
                int d2 = d  + (v & 7) - 2;
                int h2 = h  + ((v >> 3) & 7) - 2;
                int w2 = w0 + ((v >> 6) & 7) - 2;
                if ((unsigned)d2 > 3u || (unsigned)h2 > 31u || (unsigned)w2 > 31u)
                    continue;
                int n2 = (d2 << 10) | (h2 << 5) | w2;
                if (!((s_al[n2 >> 5] >> (n2 & 31)) & 1)) continue;
                float4 p = g_pos[prob][n2];
                float aai = __fadd_rn(__fadd_rn(__fmul_rn(p.x, p.x),
                                                __fmul_rn(p.y, p.y)),
                                      __fmul_rn(p.z, p.z));
                float dot = __fadd_rn(__fadd_rn(__fmul_rn(p.x, tz),
                                                __fmul_rn(p.y, ty)),
                                      __fmul_rn(p.z, tx));
                float dist = __fsub_rn(__fadd_rn(aai, bbt), __fmul_rn(2.0f, dot));
                if (dist < c2) found = true;
            }
            if (found) tp = 1;
        }
    }
    lt = __reduce_add_sync(0xFFFFFFFFu, lt);
    tp = __reduce_add_sync(0xFFFFFFFFu, tp);
    if ((tid & 31) == 0) {
        if (lt) atomicAdd(&sLT, lt);
        if (tp) atomicAdd(&sTP, tp);
    }
    __syncthreads();
    if (tid == 0) {
        if (sLT) atomicAdd(&g_cnt[prob][2], sLT);
        if (sTP) atomicAdd(&g_cnt[prob][0], sTP);
    }
}

// ---------------------------------------------------------------------------
// K5: finalize — out[prob*3 + {0,1,2}] = {tp, fp, fn} as float32
// ---------------------------------------------------------------------------
__global__ void k_final(float* __restrict__ out)
{
    int p = threadIdx.x;
    if (p < NPROB) {
        int tp = g_cnt[p][0], lp = g_cnt[p][1], lt = g_cnt[p][2];
        out[p * 3 + 0] = (float)tp;
        out[p * 3 + 1] = (float)(lp - tp);
        out[p * 3 + 2] = (float)(lt - tp);
    }
}

extern "C" void kernel_launch(void* const* d_in, const int* in_sizes, int n_in,
                              void* d_out, int out_size)
{
    const float* pred_clses = (const float*)d_in[0];
    const float* pred_boxes = (const float*)d_in[1];
    const int*   targ_clses = (const int*)d_in[2];
    const float* targ_boxes = (const float*)d_in[3];
    float* out = (float*)d_out;

    static int smem_set = 0;
    int k3_smem = (4 * NW + SEC) * sizeof(unsigned);
    if (!smem_set) {
        cudaFuncSetAttribute(k_nms, cudaFuncAttributeMaxDynamicSharedMemorySize,
                             k3_smem);
        smem_set = 1;
    }

    k_prep <<<dim3(16, NPROB), 256>>>(pred_clses, pred_boxes);
    k_edges<<<dim3(16, NPROB), 256>>>();
    k_nms  <<<NPROB, 1024, k3_smem>>>();
    k_match<<<dim3(16, NPROB), 256>>>(targ_clses, targ_boxes);
    k_final<<<1, 32>>>(out);
}